// round 11
// baseline (speedup 1.0000x reference)
#include <cuda_runtime.h>

#define G_ 4
#define T_ 2048
#define E_ 8
#define D_ 1024
#define C_ 2048
#define NTOK (G_ * T_)
#define NTOT ((long long)G_ * T_ * E_ * C_)

#define THREADS 256
#define NRB 1024                    // router blocks, 8 tokens each (1 token/warp)
#define NTB 32                      // topk blocks, one (g,e) each
#define NSPECIAL (NRB + NTB)        // 1056 specials, at bids 0,8,16,...
#define NFB 8192                    // fill blocks, 128 KB each
#define GRID (NFB + NSPECIAL)       // 9248
#define FILL_F4 8192                // float4 per fill block
#define ROUTER_WARPS (NRB * 8)      // 8192 router warps total

__device__ float g_probs[G_ * E_ * T_];   // expert-major probs
__device__ float g_zt[NTOK];              // per-token z partials
__device__ int   g_router_done;           // router warps finished
__device__ int   g_fill_done;             // fill blocks finished

__global__ void init_kernel() {
    g_router_done = 0;
    g_fill_done = 0;
}

__device__ __forceinline__ void spin_ge(volatile int* p, int target) {
    while (*p < target) __nanosleep(64);
}

// ---------------------------------------------------------------------------
// One ordinary grid, roles interleaved by blockIdx so the dependency-free
// zero-fill owns ~7/8 of wave-1 slots from t=0 while router/topk hide under
// it. Specials sit at bids {0,8,...}: special id s<32 -> topk(ge=s), else
// router block (s-32). All other bids fill.
// ---------------------------------------------------------------------------
__global__ void __launch_bounds__(THREADS, 6)
fused_kernel(const float* __restrict__ x,
             const float* __restrict__ W,
             const float* __restrict__ b,
             float* __restrict__ out) {
    __shared__ __align__(16) union {
        struct { float sW[E_ * D_]; float sb[E_]; } r;              // 32 KB
        struct { unsigned long long keys[T_]; float red[THREADS]; } t;
    } sm;

    int bid = blockIdx.x;
    int s = bid >> 3;
    bool special = ((bid & 7) == 0) && (s < NSPECIAL);

    // ============================ FILL ============================
    if (!special) {
        int f = bid - min(s + 1, NSPECIAL);          // fill rank 0..8191
        float4* out4 = reinterpret_cast<float4*>(out);
        const float4 z = make_float4(0.f, 0.f, 0.f, 0.f);
        long long base = (long long)f * FILL_F4 + threadIdx.x;
        #pragma unroll
        for (int i = 0; i < FILL_F4 / THREADS; i++)   // 32 STG.128 / thread
            out4[base + i * THREADS] = z;
        __threadfence();
        __syncthreads();
        if (threadIdx.x == 0) atomicAdd(&g_fill_done, 1);
        return;
    }

    int warp = threadIdx.x >> 5;
    int lane = threadIdx.x & 31;

    // ============================ ROUTER ============================
    if (s >= NTB) {
        for (int i = threadIdx.x; i < E_ * D_ / 4; i += THREADS)
            reinterpret_cast<float4*>(sm.r.sW)[i] =
                reinterpret_cast<const float4*>(W)[i];
        if (threadIdx.x < E_) sm.r.sb[threadIdx.x] = b[threadIdx.x];
        __syncthreads();

        int token = (s - NTB) * 8 + warp;            // 0 .. NTOK-1
        int g = token / T_;
        int t = token % T_;
        const float4* x4 = reinterpret_cast<const float4*>(x + (long long)token * D_);

        float acc[E_];
        #pragma unroll
        for (int e = 0; e < E_; e++) acc[e] = 0.f;

        #pragma unroll
        for (int i = 0; i < D_ / (32 * 4); i++) {    // 8 iterations
            int d4 = i * 32 + lane;
            float4 xv = x4[d4];
            #pragma unroll
            for (int e = 0; e < E_; e++) {
                float4 wv = reinterpret_cast<const float4*>(sm.r.sW + e * D_)[d4];
                acc[e] += xv.x * wv.x + xv.y * wv.y + xv.z * wv.z + xv.w * wv.w;
            }
        }
        #pragma unroll
        for (int o = 16; o > 0; o >>= 1)
            #pragma unroll
            for (int e = 0; e < E_; e++)
                acc[e] += __shfl_xor_sync(0xffffffffu, acc[e], o);

        float m = -1e30f;
        #pragma unroll
        for (int e = 0; e < E_; e++) { acc[e] += sm.r.sb[e]; m = fmaxf(m, acc[e]); }
        float ex[E_], sum = 0.f;
        #pragma unroll
        for (int e = 0; e < E_; e++) { ex[e] = expf(acc[e] - m); sum += ex[e]; }
        float inv = 1.f / sum;
        float lse = m + logf(sum);

        if (lane < E_)
            g_probs[(g * E_ + lane) * T_ + t] = ex[lane] * inv;
        if (lane == 0) {
            float zt = 0.f;
            #pragma unroll
            for (int e = 0; e < E_; e++) {
                float ls = acc[e] - lse;
                zt += ls * ls;
            }
            g_zt[token] = zt;
        }
        __threadfence();                 // every lane fences its own stores
        __syncwarp();
        if (lane == 0) atomicAdd(&g_router_done, 1);   // per-warp release
        return;
    }

    // ============================ TOPK ============================
    int ge = s;                // 0..31
    int e = ge & 7;
    int g = ge >> 3;

    if (threadIdx.x == 0) spin_ge(&g_router_done, ROUTER_WARPS);
    __syncthreads();
    __threadfence();

    const float* p = g_probs + (long long)ge * T_;
    for (int t = threadIdx.x; t < T_; t += THREADS) {
        unsigned int pb = __float_as_uint(p[t]);   // probs > 0 -> bits monotonic
        sm.t.keys[t] = ((unsigned long long)pb << 32) | (unsigned int)(~t);
    }
    __syncthreads();

    // bitonic sort, descending: prob desc, index asc on ties (lax.top_k order)
    for (int k = 2; k <= T_; k <<= 1) {
        for (int j = k >> 1; j > 0; j >>= 1) {
            for (int i = threadIdx.x; i < T_; i += THREADS) {
                int ixj = i ^ j;
                if (ixj > i) {
                    bool desc = ((i & k) == 0);
                    unsigned long long a = sm.t.keys[i], c = sm.t.keys[ixj];
                    if (desc ? (a < c) : (a > c)) { sm.t.keys[i] = c; sm.t.keys[ixj] = a; }
                }
            }
            __syncthreads();
        }
    }

    // block ge==0: z-loss reduction (scalar slot is NOT covered by the fill)
    if (ge == 0) {
        float acc = 0.f;
        for (int i = threadIdx.x; i < NTOK; i += THREADS)
            acc += g_zt[i];
        sm.t.red[threadIdx.x] = acc;
        __syncthreads();
        for (int o = THREADS / 2; o > 0; o >>= 1) {
            if (threadIdx.x < o) sm.t.red[threadIdx.x] += sm.t.red[threadIdx.x + o];
            __syncthreads();
        }
        if (threadIdx.x == 0)
            out[2 * NTOT] = sm.t.red[0] / (float)(G_ * T_ * E_);
    }

    // wait for the full zero-fill, then scatter this (g,e)'s nonzeros
    if (threadIdx.x == 0) spin_ge(&g_fill_done, NFB);
    __syncthreads();
    __threadfence();

    const int caps[E_] = {512, 512, 256, 256, 128, 128, 128, 128};
    int cap = caps[e];
    for (int r = threadIdx.x; r < cap; r += THREADS) {
        unsigned long long key = sm.t.keys[r];
        float gate = __uint_as_float((unsigned int)(key >> 32));
        int tok = (int)(~(unsigned int)(key & 0xffffffffu));
        long long off = (((long long)g * T_ + tok) * E_ + e) * C_ + r;
        out[off]        = 1.0f;   // dispatch_mask
        out[NTOT + off] = gate;   // combine_array
    }
}

extern "C" void kernel_launch(void* const* d_in, const int* in_sizes, int n_in,
                              void* d_out, int out_size) {
    const float* x = (const float*)d_in[0];   // token_inputs [G,T,D]
    const float* W = (const float*)d_in[1];   // [E,D]
    const float* b = (const float*)d_in[2];   // [E]
    float* out = (float*)d_out;

    init_kernel<<<1, 1>>>();
    fused_kernel<<<GRID, THREADS>>>(x, W, b, out);
}

// round 12
// speedup vs baseline: 1.0504x; 1.0504x over previous
#include <cuda_runtime.h>

#define G_ 4
#define T_ 2048
#define E_ 8
#define D_ 1024
#define C_ 2048
#define NTOK (G_ * T_)
#define NTOT ((long long)G_ * T_ * E_ * C_)

#define THREADS 256
#define NFB 8192                    // fill blocks, 128 KB each
#define NRB 1024                    // router blocks, 8 tokens each
#define GRID (NFB + NRB)            // 9216
#define FILL_F4 8192                // float4 per fill block

__device__ float g_probs[G_ * E_ * T_];   // expert-major probs
__device__ float g_zt[NTOK];              // per-token z partials

// ---------------------------------------------------------------------------
// Kernel 1: fill + router, interleaved by blockIdx, NO synchronization.
// Fill has no dependency on router; ordering vs topk/scatter comes from the
// kernel boundary. Router uses only 16.5 KB smem (W staged 4 experts/pass)
// so fill blocks keep 8 blocks/SM (64 warps) occupancy.
// ---------------------------------------------------------------------------
__global__ void __launch_bounds__(THREADS, 8)
fill_router_kernel(const float* __restrict__ x,
                   const float* __restrict__ W,
                   const float* __restrict__ b,
                   float* __restrict__ out) {
    __shared__ __align__(16) float sW[4 * D_];   // 16 KB (4 experts per pass)
    __shared__ float sb[E_];

    int bid = blockIdx.x;
    int s = bid / 9;
    bool is_router = ((bid % 9) == 0) && (s < NRB);

    // ============================ FILL ============================
    if (!is_router) {
        int f = bid - min(s + ((bid % 9) ? 1 : 0), NRB);   // 0..8191
        float4* out4 = reinterpret_cast<float4*>(out);
        const float4 z = make_float4(0.f, 0.f, 0.f, 0.f);
        long long base = (long long)f * FILL_F4 + threadIdx.x;
        #pragma unroll
        for (int i = 0; i < FILL_F4 / THREADS; i++)        // 32 STG.128/thread
            out4[base + i * THREADS] = z;
        return;
    }

    // ============================ ROUTER ============================
    int warp = threadIdx.x >> 5;
    int lane = threadIdx.x & 31;
    int token = s * 8 + warp;                 // 0 .. NTOK-1
    int g = token / T_;
    int t = token % T_;
    const float4* x4 = reinterpret_cast<const float4*>(x + (long long)token * D_);

    if (threadIdx.x < E_) sb[threadIdx.x] = b[threadIdx.x];

    float logit[E_];

    #pragma unroll
    for (int pass = 0; pass < 2; pass++) {
        __syncthreads();                      // safe to (re)stage sW
        for (int i = threadIdx.x; i < 4 * D_ / 4; i += THREADS)
            reinterpret_cast<float4*>(sW)[i] =
                reinterpret_cast<const float4*>(W + pass * 4 * D_)[i];
        __syncthreads();

        float acc[4];
        #pragma unroll
        for (int e = 0; e < 4; e++) acc[e] = 0.f;

        #pragma unroll
        for (int i = 0; i < D_ / (32 * 4); i++) {   // 8 iterations
            int d4 = i * 32 + lane;
            float4 xv = x4[d4];                      // pass 1: L1 hit
            #pragma unroll
            for (int e = 0; e < 4; e++) {
                float4 wv = reinterpret_cast<const float4*>(sW + e * D_)[d4];
                acc[e] += xv.x * wv.x + xv.y * wv.y + xv.z * wv.z + xv.w * wv.w;
            }
        }
        #pragma unroll
        for (int o = 16; o > 0; o >>= 1)
            #pragma unroll
            for (int e = 0; e < 4; e++)
                acc[e] += __shfl_xor_sync(0xffffffffu, acc[e], o);
        #pragma unroll
        for (int e = 0; e < 4; e++)
            logit[pass * 4 + e] = acc[e] + sb[pass * 4 + e];
    }

    // every lane holds all 8 logits
    float m = -1e30f;
    #pragma unroll
    for (int e = 0; e < E_; e++) m = fmaxf(m, logit[e]);
    float ex[E_], sum = 0.f;
    #pragma unroll
    for (int e = 0; e < E_; e++) { ex[e] = expf(logit[e] - m); sum += ex[e]; }
    float inv = 1.f / sum;
    float lse = m + logf(sum);

    if (lane < E_)
        g_probs[(g * E_ + lane) * T_ + t] = ex[lane] * inv;
    if (lane == 0) {
        float zt = 0.f;
        #pragma unroll
        for (int e = 0; e < E_; e++) {
            float ls = logit[e] - lse;
            zt += ls * ls;
        }
        g_zt[token] = zt;
    }
}

// ---------------------------------------------------------------------------
// Kernel 2: per-(g,e) topk (bitonic, desc prob / asc idx on ties = lax.top_k)
// + DIRECT scatter of nonzeros into the pre-zeroed output + z-loss (block 0).
// Kernel boundary orders this after the fill — no counters needed.
// ---------------------------------------------------------------------------
__global__ void topk_scatter_kernel(float* __restrict__ out) {
    __shared__ unsigned long long keys[T_];   // 16 KB
    __shared__ float red[1024];

    int ge = blockIdx.x;                      // 0..31
    int e = ge % E_;
    int g = ge / E_;

    const float* p = g_probs + (long long)ge * T_;
    for (int t = threadIdx.x; t < T_; t += blockDim.x) {
        unsigned int pb = __float_as_uint(p[t]);   // probs > 0 -> bits monotonic
        keys[t] = ((unsigned long long)pb << 32) | (unsigned int)(~t);
    }
    __syncthreads();

    for (int k = 2; k <= T_; k <<= 1) {
        for (int j = k >> 1; j > 0; j >>= 1) {
            for (int i = threadIdx.x; i < T_; i += blockDim.x) {
                int ixj = i ^ j;
                if (ixj > i) {
                    bool desc = ((i & k) == 0);
                    unsigned long long a = keys[i], c = keys[ixj];
                    if (desc ? (a < c) : (a > c)) { keys[i] = c; keys[ixj] = a; }
                }
            }
            __syncthreads();
        }
    }

    const int caps[E_] = {512, 512, 256, 256, 128, 128, 128, 128};
    int cap = caps[e];
    for (int r = threadIdx.x; r < cap; r += blockDim.x) {
        unsigned long long key = keys[r];
        float gate = __uint_as_float((unsigned int)(key >> 32));
        int tok = (int)(~(unsigned int)(key & 0xffffffffu));
        long long off = (((long long)g * T_ + tok) * E_ + e) * C_ + r;
        out[off]        = 1.0f;   // dispatch_mask
        out[NTOT + off] = gate;   // combine_array
    }

    if (ge == 0) {
        float acc = 0.f;
        for (int i = threadIdx.x; i < NTOK; i += blockDim.x)
            acc += g_zt[i];
        red[threadIdx.x] = acc;
        __syncthreads();
        for (int o = 512; o > 0; o >>= 1) {
            if (threadIdx.x < o) red[threadIdx.x] += red[threadIdx.x + o];
            __syncthreads();
        }
        if (threadIdx.x == 0)
            out[2 * NTOT] = red[0] / (float)(G_ * T_ * E_);
    }
}

extern "C" void kernel_launch(void* const* d_in, const int* in_sizes, int n_in,
                              void* d_out, int out_size) {
    const float* x = (const float*)d_in[0];   // token_inputs [G,T,D]
    const float* W = (const float*)d_in[1];   // [E,D]
    const float* b = (const float*)d_in[2];   // [E]
    float* out = (float*)d_out;

    fill_router_kernel<<<GRID, THREADS>>>(x, W, b, out);
    topk_scatter_kernel<<<G_ * E_, 1024>>>(out);
}

// round 13
// speedup vs baseline: 1.2479x; 1.1880x over previous
#include <cuda_runtime.h>

#define G_ 4
#define T_ 2048
#define E_ 8
#define D_ 1024
#define C_ 2048
#define NTOK (G_ * T_)
#define NTOT ((long long)G_ * T_ * E_ * C_)

__device__ float g_probs[G_ * E_ * T_];   // expert-major probs
__device__ float g_zt[NTOK];              // per-token z partials
__device__ float g_zsum;                  // reduced sum (written by topk)
__device__ int   g_tok [G_ * E_ * C_];    // rank table: token index or -1
__device__ float g_gate[G_ * E_ * C_];    // rank table: gate value

// ---------------------------------------------------------------------------
// Kernel 1: router (r10, measured 20 us). 8 warps/block, 2 tokens per warp.
// ---------------------------------------------------------------------------
__global__ void router_kernel(const float* __restrict__ x,
                              const float* __restrict__ W,
                              const float* __restrict__ b) {
    __shared__ float sW[E_ * D_];   // 32 KB
    __shared__ float sb[E_];

    for (int i = threadIdx.x; i < E_ * D_ / 4; i += blockDim.x)
        reinterpret_cast<float4*>(sW)[i] = reinterpret_cast<const float4*>(W)[i];
    if (threadIdx.x < E_) sb[threadIdx.x] = b[threadIdx.x];
    __syncthreads();

    int warp = threadIdx.x >> 5;
    int lane = threadIdx.x & 31;
    int t0 = blockIdx.x * 16 + warp * 2;
    int t1 = t0 + 1;
    int g = t0 / T_;
    int tt0 = t0 % T_, tt1 = t1 % T_;

    const float4* x4a = reinterpret_cast<const float4*>(x + (long long)t0 * D_);
    const float4* x4b = reinterpret_cast<const float4*>(x + (long long)t1 * D_);

    float acc0[E_], acc1[E_];
    #pragma unroll
    for (int e = 0; e < E_; e++) { acc0[e] = 0.f; acc1[e] = 0.f; }

    #pragma unroll
    for (int i = 0; i < D_ / (32 * 4); i++) {
        int d4 = i * 32 + lane;
        float4 xv0 = x4a[d4];
        float4 xv1 = x4b[d4];
        #pragma unroll
        for (int e = 0; e < E_; e++) {
            float4 wv = reinterpret_cast<const float4*>(sW + e * D_)[d4];
            acc0[e] += xv0.x * wv.x + xv0.y * wv.y + xv0.z * wv.z + xv0.w * wv.w;
            acc1[e] += xv1.x * wv.x + xv1.y * wv.y + xv1.z * wv.z + xv1.w * wv.w;
        }
    }
    #pragma unroll
    for (int o = 16; o > 0; o >>= 1) {
        #pragma unroll
        for (int e = 0; e < E_; e++) {
            acc0[e] += __shfl_xor_sync(0xffffffffu, acc0[e], o);
            acc1[e] += __shfl_xor_sync(0xffffffffu, acc1[e], o);
        }
    }

    float m0 = -1e30f, m1 = -1e30f;
    #pragma unroll
    for (int e = 0; e < E_; e++) {
        acc0[e] += sb[e]; acc1[e] += sb[e];
        m0 = fmaxf(m0, acc0[e]); m1 = fmaxf(m1, acc1[e]);
    }
    float ex0[E_], ex1[E_], s0 = 0.f, s1 = 0.f;
    #pragma unroll
    for (int e = 0; e < E_; e++) {
        ex0[e] = expf(acc0[e] - m0); s0 += ex0[e];
        ex1[e] = expf(acc1[e] - m1); s1 += ex1[e];
    }
    float inv0 = 1.f / s0, inv1 = 1.f / s1;
    float lse0 = m0 + logf(s0), lse1 = m1 + logf(s1);

    if (lane < E_)
        g_probs[(g * E_ + lane) * T_ + tt0] = ex0[lane] * inv0;
    else if (lane < 2 * E_)
        g_probs[(g * E_ + (lane - E_)) * T_ + tt1] = ex1[lane - E_] * inv1;

    if (lane == 0) {
        float z0 = 0.f, z1 = 0.f;
        #pragma unroll
        for (int e = 0; e < E_; e++) {
            float a = acc0[e] - lse0, c = acc1[e] - lse1;
            z0 += a * a; z1 += c * c;
        }
        g_zt[t0] = z0;
        g_zt[t1] = z1;
    }
}

// ---------------------------------------------------------------------------
// Kernel 2: topk via register/shuffle bitonic sort. Thread t holds elements
// {2t, 2t+1} in registers. j==1: intra-thread; j=2..32: shfl_xor; j>=64:
// shared (only 15 of 66 stages). Descending => prob desc, idx asc on ties
// (matches jax.lax.top_k). Emits rank tables; block 0 reduces z.
// ---------------------------------------------------------------------------
__global__ void topk_kernel() {
    __shared__ unsigned long long s[T_];   // 16 KB (shared stages only)
    __shared__ float red[1024];

    int ge = blockIdx.x;                   // 0..31
    int e = ge % E_;
    int t = threadIdx.x;                   // 0..1023
    int lane = t & 31;
    int i0 = 2 * t, i1 = 2 * t + 1;

    const float* p = g_probs + (long long)ge * T_;
    unsigned long long e0 =
        ((unsigned long long)__float_as_uint(p[i0]) << 32) | (unsigned int)(~i0);
    unsigned long long e1 =
        ((unsigned long long)__float_as_uint(p[i1]) << 32) | (unsigned int)(~i1);

    #pragma unroll
    for (int k = 2; k <= T_; k <<= 1) {
        bool desc = ((i0 & k) == 0);       // same for i1 (they differ in bit0; k>=2)

        // shared-memory stages: j >= 64
        for (int j = k >> 1; j >= 64; j >>= 1) {
            s[i0] = e0; s[i1] = e1;
            __syncthreads();
            unsigned long long p0 = s[i0 ^ j], p1 = s[i1 ^ j];
            bool lower = ((i0 & j) == 0);  // j>=64: same for both slots
            bool keepmax = (desc == lower);
            e0 = keepmax ? (e0 > p0 ? e0 : p0) : (e0 < p0 ? e0 : p0);
            e1 = keepmax ? (e1 > p1 ? e1 : p1) : (e1 < p1 ? e1 : p1);
            __syncthreads();
        }
        // shuffle stages: j = 32 .. 2 (partner lane = lane ^ (j/2), within warp)
        #pragma unroll
        for (int j = (k >> 1) >= 32 ? 32 : (k >> 1); j >= 2; j >>= 1) {
            unsigned long long p0 = __shfl_xor_sync(0xffffffffu, e0, j >> 1);
            unsigned long long p1 = __shfl_xor_sync(0xffffffffu, e1, j >> 1);
            bool lower = ((lane & (j >> 1)) == 0);
            bool keepmax = (desc == lower);
            e0 = keepmax ? (e0 > p0 ? e0 : p0) : (e0 < p0 ? e0 : p0);
            e1 = keepmax ? (e1 > p1 ? e1 : p1) : (e1 < p1 ? e1 : p1);
        }
        // j == 1: intra-thread pair (i0, i1)
        {
            unsigned long long mx = (e0 > e1) ? e0 : e1;
            unsigned long long mn = (e0 > e1) ? e1 : e0;
            e0 = desc ? mx : mn;
            e1 = desc ? mn : mx;
        }
    }

    // ranks i0, i1 now live in registers; emit compact rank tables
    const int caps[E_] = {512, 512, 256, 256, 128, 128, 128, 128};
    int cap = caps[e];

    if (i0 < cap) {
        g_gate[ge * C_ + i0] = __uint_as_float((unsigned int)(e0 >> 32));
        g_tok [ge * C_ + i0] = (int)(~(unsigned int)(e0 & 0xffffffffu));
    } else {
        g_gate[ge * C_ + i0] = 0.f;
        g_tok [ge * C_ + i0] = -1;
    }
    if (i1 < cap) {
        g_gate[ge * C_ + i1] = __uint_as_float((unsigned int)(e1 >> 32));
        g_tok [ge * C_ + i1] = (int)(~(unsigned int)(e1 & 0xffffffffu));
    } else {
        g_gate[ge * C_ + i1] = 0.f;
        g_tok [ge * C_ + i1] = -1;
    }

    if (blockIdx.x == 0) {
        float acc = 0.f;
        for (int i = t; i < NTOK; i += 1024)
            acc += g_zt[i];
        red[t] = acc;
        __syncthreads();
        for (int o = 512; o > 0; o >>= 1) {
            if (t < o) red[t] += red[t + o];
            __syncthreads();
        }
        if (t == 0) g_zsum = red[0];
    }
}

// ---------------------------------------------------------------------------
// Kernel 3: fused materialize (r10, measured fastest fill ~145-150 us).
// Block = (g, e, c-half, 16-token chunk); table slice in registers.
// ---------------------------------------------------------------------------
__global__ void materialize_kernel(float* __restrict__ out) {
    int B = blockIdx.x;
    int tch   = B & 127;
    int rest  = B >> 7;
    int chalf = rest & 1;
    int ge    = rest >> 1;
    int e = ge & 7;
    int g = ge >> 3;

    int c4 = chalf * 256 + threadIdx.x;
    int4   tok4  = reinterpret_cast<const int4*  >(g_tok )[ge * (C_ / 4) + c4];
    float4 gate4 = reinterpret_cast<const float4*>(g_gate)[ge * (C_ / 4) + c4];

    const long long NTOT4 = NTOT / 4;
    float4* out4 = reinterpret_cast<float4*>(out);

    int tbase = tch * 16;
    #pragma unroll
    for (int i = 0; i < 16; i++) {
        int t = tbase + i;
        long long off = (((long long)g * T_ + t) * E_ + e) * (C_ / 4) + c4;
        float4 d, c;
        d.x = (tok4.x == t) ? 1.f : 0.f;  c.x = (tok4.x == t) ? gate4.x : 0.f;
        d.y = (tok4.y == t) ? 1.f : 0.f;  c.y = (tok4.y == t) ? gate4.y : 0.f;
        d.z = (tok4.z == t) ? 1.f : 0.f;  c.z = (tok4.z == t) ? gate4.z : 0.f;
        d.w = (tok4.w == t) ? 1.f : 0.f;  c.w = (tok4.w == t) ? gate4.w : 0.f;
        out4[off]         = d;   // dispatch_mask
        out4[off + NTOT4] = c;   // combine_array
    }

    if (B == 0 && threadIdx.x == 0)
        out[2 * NTOT] = g_zsum / (float)(G_ * T_ * E_);   // router_z_loss
}

extern "C" void kernel_launch(void* const* d_in, const int* in_sizes, int n_in,
                              void* d_out, int out_size) {
    const float* x = (const float*)d_in[0];   // token_inputs [G,T,D]
    const float* W = (const float*)d_in[1];   // [E,D]
    const float* b = (const float*)d_in[2];   // [E]
    float* out = (float*)d_out;

    router_kernel<<<NTOK / 16, 256>>>(x, W, b);
    topk_kernel<<<G_ * E_, 1024>>>();
    materialize_kernel<<<G_ * E_ * 2 * (T_ / 16), 256>>>(out);
}